// round 15
// baseline (speedup 1.0000x reference)
#include <cuda_runtime.h>
#include <cuda_bf16.h>
#include <cstdint>

// GriddingDistance round 15: memset for zero-fill (6.7TB/s DMA path; the
// hand-rolled STG kernel ceilings at 4.8TB/s) + PDL only on the K1->K2 edge.
//   L0 cudaMemsetAsync pred half
//   K1 pred scatter || gt zero. Scatter blocks trigger launch_dependents
//      right after issuing their REDs (pred-grid visibility irrelevant to
//      K2); zero blocks fence-then-trigger (gt zeros must be visible).
//      => K2 launches during K1's CTA-spread tail, bounded overlap only.
//   K2 (PSS) gt scatter: loads+math pre-wait, REDs post-wait.
// Scatter math = round-5 winner (z-window v2/v4 vector REDs).

#define GRID_R 128
#define GSZ    (GRID_R * GRID_R * GRID_R)

__device__ __forceinline__ void pdl_wait() {
    asm volatile("griddepcontrol.wait;" ::: "memory");
}
__device__ __forceinline__ void pdl_trigger() {
    asm volatile("griddepcontrol.launch_dependents;");
}

__device__ __forceinline__ void red_add_f32(float* p, float v) {
    atomicAdd(p, v);  // return unused -> REDG
}
__device__ __forceinline__ void red_add_v2_f32(float* p, float a, float b) {
    asm volatile("red.global.add.v2.f32 [%0], {%1, %2};"
                 :: "l"(p), "f"(a), "f"(b) : "memory");
}
__device__ __forceinline__ void red_add_v4_f32(float* p, float a, float b,
                                               float c, float d) {
    asm volatile("red.global.add.v4.f32 [%0], {%1, %2, %3, %4};"
                 :: "l"(p), "f"(a), "f"(b), "f"(c), "f"(d) : "memory");
}

// Scatter one point. If WAIT, griddepcontrol.wait sits after all arithmetic,
// immediately before the REDs.
template <bool WAIT>
__device__ __forceinline__ void scatter_point(float px, float py, float pz,
                                              float* __restrict__ gb)
{
    px = fmaf(px, 128.0f, 64.0f);
    py = fmaf(py, 128.0f, 64.0f);
    pz = fmaf(pz, 128.0f, 64.0f);

    float fx = floorf(px), fy = floorf(py), fz = floorf(pz);
    float dx = px - fx,   dy = py - fy,   dz = pz - fz;
    int ix = (int)fx, iy = (int)fy, iz = (int)fz;

    float wx0 = 1.0f - dx, wy0 = 1.0f - dy, wz0 = 1.0f - dz;
    float w00 = wx0 * wy0, w01 = wx0 * dy, w10 = dx * wy0, w11 = dx * dy;

    bool interior = (ix >= 0) & (ix + 1 < GRID_R) &
                    (iy >= 0) & (iy + 1 < GRID_R) &
                    (iz >= 0) & (iz + 1 < GRID_R);

    if (interior) {
        int r00 = (ix * GRID_R + iy) * GRID_R + iz;
        int r01 = r00 + GRID_R;
        int r10 = r00 + GRID_R * GRID_R;
        int r11 = r10 + GRID_R;

        float a00 = w00 * wz0, b00 = w00 * dz;
        float a01 = w01 * wz0, b01 = w01 * dz;
        float a10 = w10 * wz0, b10 = w10 * dz;
        float a11 = w11 * wz0, b11 = w11 * dz;

        if (WAIT) pdl_wait();

        int m4 = iz & 3;
        if ((m4 & 1) == 0) {
            red_add_v2_f32(gb + r00, a00, b00);
            red_add_v2_f32(gb + r01, a01, b01);
            red_add_v2_f32(gb + r10, a10, b10);
            red_add_v2_f32(gb + r11, a11, b11);
        } else if (m4 == 1) {
            red_add_v4_f32(gb + r00 - 1, 0.f, a00, b00, 0.f);
            red_add_v4_f32(gb + r01 - 1, 0.f, a01, b01, 0.f);
            red_add_v4_f32(gb + r10 - 1, 0.f, a10, b10, 0.f);
            red_add_v4_f32(gb + r11 - 1, 0.f, a11, b11, 0.f);
        } else {
            red_add_f32(gb + r00,     a00);
            red_add_f32(gb + r00 + 1, b00);
            red_add_f32(gb + r01,     a01);
            red_add_f32(gb + r01 + 1, b01);
            red_add_f32(gb + r10,     a10);
            red_add_f32(gb + r10 + 1, b10);
            red_add_f32(gb + r11,     a11);
            red_add_f32(gb + r11 + 1, b11);
        }
    } else {
        int ix0 = min(max(ix,     0), GRID_R - 1);
        int ix1 = min(max(ix + 1, 0), GRID_R - 1);
        int iy0 = min(max(iy,     0), GRID_R - 1);
        int iy1 = min(max(iy + 1, 0), GRID_R - 1);
        int iz0 = min(max(iz,     0), GRID_R - 1);
        int iz1 = min(max(iz + 1, 0), GRID_R - 1);
        int rx0 = ix0 * GRID_R * GRID_R, rx1 = ix1 * GRID_R * GRID_R;
        int ry0 = iy0 * GRID_R,          ry1 = iy1 * GRID_R;

        if (WAIT) pdl_wait();

        red_add_f32(gb + (rx0 + ry0 + iz0), w00 * wz0);
        red_add_f32(gb + (rx0 + ry0 + iz1), w00 * dz);
        red_add_f32(gb + (rx0 + ry1 + iz0), w01 * wz0);
        red_add_f32(gb + (rx0 + ry1 + iz1), w01 * dz);
        red_add_f32(gb + (rx1 + ry0 + iz0), w10 * wz0);
        red_add_f32(gb + (rx1 + ry0 + iz1), w10 * dz);
        red_add_f32(gb + (rx1 + ry1 + iz0), w11 * wz0);
        red_add_f32(gb + (rx1 + ry1 + iz1), w11 * dz);
    }
}

// K1: y==0 scatter pred (no wait; follows memset via normal stream order),
//     trigger after REDs are issued (no fence; K2 doesn't read pred grid).
//     y==1 zero gt half, fence + trigger (K2's atomics need these zeros).
__global__ __launch_bounds__(256)
void scatter_pred_zero_gt_kernel(const float* __restrict__ pred,
                                 float* __restrict__ out,
                                 int n_per_sample,
                                 int total_points,
                                 long long grid_per_cloud)
{
    if (blockIdx.y == 0) {
        int t = blockIdx.x * blockDim.x + threadIdx.x;
        if (t < total_points) {
            const float* p = pred + 3 * t;
            float px = p[0], py = p[1], pz = p[2];
            int sample = t / n_per_sample;
            scatter_point<false>(px, py, pz, out + (long long)sample * GSZ);
        }
        pdl_trigger();                         // early: lets K2 launch in tail
    } else {
        float4* z = (float4*)(out + grid_per_cloud);
        unsigned n4 = (unsigned)(grid_per_cloud >> 2);
        unsigned stride = gridDim.x * blockDim.x;
        float4 zero = make_float4(0.f, 0.f, 0.f, 0.f);
        for (unsigned i = blockIdx.x * blockDim.x + threadIdx.x;
             i < n4; i += stride)
            z[i] = zero;
        __threadfence();                       // zeros visible before K2 REDs
        pdl_trigger();
    }
}

// K2: gt scatter, deep prologue (loads+math pre-wait, REDs post-wait).
__global__ __launch_bounds__(256)
void scatter_gt_kernel(const float* __restrict__ gt,
                       float* __restrict__ g,
                       int n_per_sample,
                       int total_points)
{
    int t = blockIdx.x * blockDim.x + threadIdx.x;
    if (t < total_points) {
        const float* p = gt + 3 * t;
        float px = p[0], py = p[1], pz = p[2];
        int sample = t / n_per_sample;
        scatter_point<true>(px, py, pz, g + (long long)sample * GSZ);
    } else {
        pdl_wait();
    }
}

extern "C" void kernel_launch(void* const* d_in, const int* in_sizes, int n_in,
                              void* d_out, int out_size)
{
    const float* pred = (const float*)d_in[0];
    const float* gt   = (const float*)d_in[1];
    float* out = (float*)d_out;

    int b = out_size / (2 * GSZ);                      // 8
    int total_points = in_sizes[0] / 3;                // 524288
    int n = total_points / b;                          // 65536
    long long grid_per_cloud = (long long)b * GSZ;     // 16777216 floats

    int nblk = (total_points + 255) / 256;             // 2048

    // L0: zero pred half on the fast memset path
    cudaMemsetAsync(out, 0, (size_t)grid_per_cloud * sizeof(float));

    // K1: pred scatter || gt zero (normal launch; full dependency on memset)
    scatter_pred_zero_gt_kernel<<<dim3(nblk, 2), 256>>>(
        pred, out, n, total_points, grid_per_cloud);

    // K2: gt scatter with programmatic dependency on K1
    {
        cudaLaunchConfig_t cfg = {};
        cudaLaunchAttribute attr[1];
        attr[0].id = cudaLaunchAttributeProgrammaticStreamSerialization;
        attr[0].val.programmaticStreamSerializationAllowed = 1;
        cfg.attrs = attr;
        cfg.numAttrs = 1;
        cfg.gridDim = dim3(nblk, 1, 1);
        cfg.blockDim = dim3(256, 1, 1);
        cfg.stream = 0;
        cudaLaunchKernelEx(&cfg, scatter_gt_kernel,
                           gt, out + grid_per_cloud, n, total_points);
    }
}